// round 1
// baseline (speedup 1.0000x reference)
#include <cuda_runtime.h>
#include <cstddef>

// Problem dims (fixed by the dataset)
#define VTH 1.0f
constexpr int TT     = 4;      // timesteps
constexpr int BNROWS = 8192;   // B*N
constexpr int DD     = 512;
constexpr int HH     = 2048;

// Tiling
constexpr int BM  = 64;   // bn rows per block
constexpr int BNC = 64;   // output cols per block
constexpr int BK  = 16;   // k per stage
constexpr int PAD = 4;    // smem row padding

// Scratch: s1 spikes [T][BN][H] fp32 (256 MiB static device array — allowed)
__device__ float g_s1[(size_t)TT * BNROWS * HH];

// Fused GEMM + PLIF scan.
//   A   : [T][BNROWS][K]  (activations per timestep)
//   W   : [N][K]          (weight, row-major, used as B^T)
//   out : [T][BNROWS][N]  (spikes, 0.0/1.0 fp32)
// Computes acc[t] = A[t]·W^T for a 64x64 tile with all 4 timesteps in
// registers, then runs the PLIF scan (v += a*(x-v); spike; hard reset)
// in-register and stores spikes directly.
__global__ __launch_bounds__(256, 2)
void fused_gemm_plif(const float* __restrict__ A,
                     const float* __restrict__ W,
                     const float* __restrict__ alphap,
                     float* __restrict__ out,
                     int K, int N)
{
    __shared__ float As[2][TT][BK][BM + PAD];
    __shared__ float Bs[2][BK][BNC + PAD];

    const int tid = threadIdx.x;
    const int bm0 = blockIdx.x * BM;
    const int bn0 = blockIdx.y * BNC;

    // 16x16 thread grid of 4x4 micro-tiles
    const int tx   = tid & 15;
    const int ty   = tid >> 4;
    const int col0 = tx * 4;
    const int row0 = ty * 4;

    // A-load mapping: one (t,row) pair per thread, 16 k-floats each
    const int tA = tid >> 6;     // 0..3  (timestep)
    const int rA = tid & 63;     // 0..63 (bn row within tile)
    // B-load mapping: one row, 4 k-floats each
    const int rB = tid >> 2;         // 0..63 (output col / weight row)
    const int cB = (tid & 3) * 4;    // k offset

    const float* Ap = A + ((size_t)tA * BNROWS + (bm0 + rA)) * (size_t)K;
    const float* Wp = W + (size_t)(bn0 + rB) * (size_t)K + cB;

    float acc[TT][4][4];
#pragma unroll
    for (int t = 0; t < TT; t++)
#pragma unroll
        for (int i = 0; i < 4; i++)
#pragma unroll
            for (int j = 0; j < 4; j++) acc[t][i][j] = 0.f;

    const int nk = K / BK;

    // Prologue: stage 0 into smem (transposed, padded)
    {
#pragma unroll
        for (int c = 0; c < 4; c++) {
            float4 v = *(const float4*)(Ap + c * 4);
            As[0][tA][c * 4 + 0][rA] = v.x;
            As[0][tA][c * 4 + 1][rA] = v.y;
            As[0][tA][c * 4 + 2][rA] = v.z;
            As[0][tA][c * 4 + 3][rA] = v.w;
        }
        float4 v = *(const float4*)(Wp);
        Bs[0][cB + 0][rB] = v.x;
        Bs[0][cB + 1][rB] = v.y;
        Bs[0][cB + 2][rB] = v.z;
        Bs[0][cB + 3][rB] = v.w;
    }
    __syncthreads();

    int buf = 0;
    for (int kt = 0; kt < nk; kt++) {
        float4 pa[4];
        float4 pb;
        const bool has_next = (kt + 1 < nk);
        if (has_next) {
            const float* Ap2 = Ap + (size_t)(kt + 1) * BK;
#pragma unroll
            for (int c = 0; c < 4; c++) pa[c] = *(const float4*)(Ap2 + c * 4);
            pb = *(const float4*)(Wp + (size_t)(kt + 1) * BK);
        }

#pragma unroll
        for (int k = 0; k < BK; k++) {
            float4 bv = *(const float4*)&Bs[buf][k][col0];
            float4 av[TT];
#pragma unroll
            for (int t = 0; t < TT; t++)
                av[t] = *(const float4*)&As[buf][t][k][row0];
#pragma unroll
            for (int t = 0; t < TT; t++) {
                float ai0 = av[t].x, ai1 = av[t].y, ai2 = av[t].z, ai3 = av[t].w;
                acc[t][0][0] += ai0 * bv.x; acc[t][0][1] += ai0 * bv.y;
                acc[t][0][2] += ai0 * bv.z; acc[t][0][3] += ai0 * bv.w;
                acc[t][1][0] += ai1 * bv.x; acc[t][1][1] += ai1 * bv.y;
                acc[t][1][2] += ai1 * bv.z; acc[t][1][3] += ai1 * bv.w;
                acc[t][2][0] += ai2 * bv.x; acc[t][2][1] += ai2 * bv.y;
                acc[t][2][2] += ai2 * bv.z; acc[t][2][3] += ai2 * bv.w;
                acc[t][3][0] += ai3 * bv.x; acc[t][3][1] += ai3 * bv.y;
                acc[t][3][2] += ai3 * bv.z; acc[t][3][3] += ai3 * bv.w;
            }
        }

        if (has_next) {
            const int nb = buf ^ 1;
#pragma unroll
            for (int c = 0; c < 4; c++) {
                As[nb][tA][c * 4 + 0][rA] = pa[c].x;
                As[nb][tA][c * 4 + 1][rA] = pa[c].y;
                As[nb][tA][c * 4 + 2][rA] = pa[c].z;
                As[nb][tA][c * 4 + 3][rA] = pa[c].w;
            }
            Bs[nb][cB + 0][rB] = pb.x;
            Bs[nb][cB + 1][rB] = pb.y;
            Bs[nb][cB + 2][rB] = pb.z;
            Bs[nb][cB + 3][rB] = pb.w;
            __syncthreads();
        }
        buf ^= 1;
    }

    // PLIF scan over t (in-place: acc becomes spikes)
    const float a = *alphap;
#pragma unroll
    for (int i = 0; i < 4; i++)
#pragma unroll
        for (int j = 0; j < 4; j++) {
            float v = 0.f;
#pragma unroll
            for (int t = 0; t < TT; t++) {
                v += a * (acc[t][i][j] - v);       // leaky integrate
                float sp = (v >= VTH) ? 1.f : 0.f; // Heaviside(v - v_th)
                acc[t][i][j] = sp;
                v = (sp != 0.f) ? 0.f : v;         // hard reset
            }
        }

    // Store spikes
#pragma unroll
    for (int t = 0; t < TT; t++)
#pragma unroll
        for (int i = 0; i < 4; i++) {
            float4 v = make_float4(acc[t][i][0], acc[t][i][1],
                                   acc[t][i][2], acc[t][i][3]);
            *(float4*)(out + ((size_t)t * BNROWS + (bm0 + row0 + i)) * (size_t)N
                           + bn0 + col0) = v;
        }
}

extern "C" void kernel_launch(void* const* d_in, const int* in_sizes, int n_in,
                              void* d_out, int out_size)
{
    const float* x  = (const float*)d_in[0];   // [T,B,N,D]
    const float* W1 = (const float*)d_in[1];   // [H,D]
    const float* W2 = (const float*)d_in[2];   // [D,H]
    const float* a1 = (const float*)d_in[3];   // [1]
    const float* a2 = (const float*)d_in[4];   // [1]
    float* out = (float*)d_out;                // [T,B,N,D]

    float* s1p = nullptr;
    cudaGetSymbolAddress((void**)&s1p, g_s1);

    // Layer 1: h = x·W1^T, PLIF -> s1   (K=512, N=2048)
    dim3 g1(BNROWS / BM, HH / BNC);   // 128 x 32
    fused_gemm_plif<<<g1, 256>>>(x, W1, a1, s1p, DD, HH);

    // Layer 2: y = s1·W2^T, PLIF -> out (K=2048, N=512)
    dim3 g2(BNROWS / BM, DD / BNC);   // 128 x 8
    fused_gemm_plif<<<g2, 256>>>(s1p, W2, a2, out, HH, DD);
}

// round 3
// speedup vs baseline: 3.1815x; 3.1815x over previous
#include <cuda_runtime.h>
#include <cuda_bf16.h>
#include <cstdint>
#include <cstddef>

// ---------------- problem dims ----------------
constexpr int TT    = 4;
constexpr int BROWS = 8192;           // B*N
constexpr int DD    = 512;
constexpr int HH    = 2048;
constexpr int KA1   = 1024;           // layer1 A cols: [hi(512) | lo(512)]
constexpr int KB1   = 1536;           // layer1 extended K
constexpr int KA2   = 2048;           // layer2 A cols (s1, exact bf16)
constexpr int KB2   = 4096;           // layer2 extended K: W2 [hi|lo]

// tile config
constexpr int MS = 64;    // sites (b,n rows) per CTA
constexpr int TN = 128;   // output cols per CTA
constexpr int BK = 64;    // k per smem stage (128 bytes bf16)

// smem: A 2 bufs x (4t x 64 sites x 128B) = 65536 ; B 2 bufs x (128 x 128B) = 32768
constexpr uint32_t SM_B_OFF   = 65536;
constexpr uint32_t SMEM_BYTES = 98304;

// ---------------- scratch (static device arrays) ----------------
__device__ __nv_bfloat16 g_xs[(size_t)TT * BROWS * KA1];   // x split [hi|lo]
__device__ __nv_bfloat16 g_w1[(size_t)HH * KB1];           // [hi|hi|lo]
__device__ __nv_bfloat16 g_w2[(size_t)DD * KB2];           // [hi|lo]
__device__ __nv_bfloat16 g_s1[(size_t)TT * BROWS * HH];    // spikes layer1 (exact)

// ---------------- PTX helpers ----------------
__device__ __forceinline__ uint32_t smem_u32(const void* p) {
    uint32_t a;
    asm("{ .reg .u64 t; cvta.to.shared.u64 t, %1; cvt.u32.u64 %0, t; }" : "=r"(a) : "l"(p));
    return a;
}
#define CP_ASYNC16(dst, src) \
    asm volatile("cp.async.cg.shared.global [%0], [%1], 16;" :: "r"(dst), "l"(src) : "memory")
#define CP_COMMIT() asm volatile("cp.async.commit_group;" ::: "memory")
#define CP_WAIT1()  asm volatile("cp.async.wait_group 1;" ::: "memory")
#define CP_WAIT0()  asm volatile("cp.async.wait_group 0;" ::: "memory")

#define LDSM_X4(r0, r1, r2, r3, addr)                                        \
    asm volatile("ldmatrix.sync.aligned.m8n8.x4.shared.b16 {%0,%1,%2,%3}, [%4];" \
        : "=r"(r0), "=r"(r1), "=r"(r2), "=r"(r3) : "r"(addr))

#define MMA16816(d, a, b)                                                    \
    asm volatile("mma.sync.aligned.m16n8k16.row.col.f32.bf16.bf16.f32 "      \
        "{%0,%1,%2,%3}, {%4,%5,%6,%7}, {%8,%9}, {%0,%1,%2,%3};"              \
        : "+f"((d)[0]), "+f"((d)[1]), "+f"((d)[2]), "+f"((d)[3])             \
        : "r"((a)[0]), "r"((a)[1]), "r"((a)[2]), "r"((a)[3]),                \
          "r"((b)[0]), "r"((b)[1]))

// smem offsets with XOR swizzle: 128B rows, 8 x 16B segments, kseg ^= row&7
__device__ __forceinline__ uint32_t a_off(int buf, int t, int site, int kseg) {
    return buf * 32768 + t * 8192 + site * 128 + ((kseg ^ (site & 7)) << 4);
}
__device__ __forceinline__ uint32_t b_off(int buf, int n, int kseg) {
    return SM_B_OFF + buf * 16384 + n * 128 + ((kseg ^ (n & 7)) << 4);
}

// ---------------- split/pack kernels ----------------
__global__ void split_x_kernel(const float* __restrict__ x, __nv_bfloat16* __restrict__ xs)
{
    size_t i = (size_t)blockIdx.x * blockDim.x + threadIdx.x;   // 32768*512
    int r = (int)(i >> 9);
    int d = (int)(i & 511);
    float v = x[i];
    __nv_bfloat16 hi = __float2bfloat16(v);
    float lo = v - __bfloat162float(hi);
    xs[(size_t)r * KA1 + d]       = hi;
    xs[(size_t)r * KA1 + 512 + d] = __float2bfloat16(lo);
}
__global__ void pack_w1_kernel(const float* __restrict__ w, __nv_bfloat16* __restrict__ o)
{
    size_t i = (size_t)blockIdx.x * blockDim.x + threadIdx.x;   // 2048*512
    int r = (int)(i >> 9);
    int d = (int)(i & 511);
    float v = w[i];
    __nv_bfloat16 hi = __float2bfloat16(v);
    float lo = v - __bfloat162float(hi);
    o[(size_t)r * KB1 + d]        = hi;
    o[(size_t)r * KB1 + 512 + d]  = hi;
    o[(size_t)r * KB1 + 1024 + d] = __float2bfloat16(lo);
}
__global__ void pack_w2_kernel(const float* __restrict__ w, __nv_bfloat16* __restrict__ o)
{
    size_t i = (size_t)blockIdx.x * blockDim.x + threadIdx.x;   // 512*2048
    int r = (int)(i >> 11);
    int c = (int)(i & 2047);
    float v = w[i];
    __nv_bfloat16 hi = __float2bfloat16(v);
    float lo = v - __bfloat162float(hi);
    o[(size_t)r * KB2 + c]        = hi;
    o[(size_t)r * KB2 + 2048 + c] = __float2bfloat16(lo);
}

// ---------------- fused mma.sync GEMM + PLIF ----------------
// A [TT][BROWS][KA] bf16 (K wraps mod KA), Bw [NG][KB] bf16 (row n, k contig).
// out: spikes, bf16 (OUTF32=0) or fp32 (OUTF32=1), [TT][BROWS][NG].
template<int OUTF32>
__global__ __launch_bounds__(256, 1)
void gemm_plif(const __nv_bfloat16* __restrict__ A,
               const __nv_bfloat16* __restrict__ Bw,
               const float* __restrict__ alphap,
               void* __restrict__ outp,
               int KA, int KB, int NG)
{
    extern __shared__ __align__(128) unsigned char smem_raw[];
    const uint32_t sbase = smem_u32(smem_raw);

    const int tid  = threadIdx.x;
    const int lane = tid & 31;
    const int wid  = tid >> 5;          // 0..7
    const int wm   = wid & 1;           // 2 warps over sites
    const int wn   = wid >> 1;          // 4 warps over cols
    const int sm_w = wm * 32;           // warp site base (0 or 32)
    const int nn_w = wn * 32;           // warp col base

    const int bm0 = blockIdx.x * MS;
    const int bn0 = blockIdx.y * TN;

    const int NC = KB / BK;

    // chunk loader
    auto load_chunk = [&](int cc, int buf) {
        const int acol = (cc * BK) % KA;
        const int bcol = cc * BK;
        #pragma unroll
        for (int i = tid; i < 2048; i += 256) {      // A: 4t*64*8 segs
            int kseg = i & 7, site = (i >> 3) & 63, t = i >> 9;
            const __nv_bfloat16* g =
                A + ((size_t)t * BROWS + bm0 + site) * KA + acol + kseg * 8;
            CP_ASYNC16(sbase + a_off(buf, t, site, kseg), g);
        }
        #pragma unroll
        for (int i = tid; i < 1024; i += 256) {      // B: 128*8 segs
            int kseg = i & 7, n = i >> 3;
            const __nv_bfloat16* g =
                Bw + (size_t)(bn0 + n) * KB + bcol + kseg * 8;
            CP_ASYNC16(sbase + b_off(buf, n, kseg), g);
        }
        CP_COMMIT();
    };

    float acc[TT][2][4][4];     // [t][mtile][ntile][4]
    #pragma unroll
    for (int t = 0; t < TT; t++)
        #pragma unroll
        for (int m = 0; m < 2; m++)
            #pragma unroll
            for (int n = 0; n < 4; n++)
                #pragma unroll
                for (int e = 0; e < 4; e++) acc[t][m][n][e] = 0.f;

    load_chunk(0, 0);
    load_chunk(1, 1);

    // ldmatrix lane addressing (precomputed parts)
    const int a_row_l = lane & 15;        // + site base
    const int a_ks_l  = lane >> 4;        // 0/1
    const int b_row_l = (lane & 7) + ((lane & 16) >> 1);  // + n base
    const int b_ks_l  = (lane >> 3) & 1;

    for (int cc = 0; cc < NC; cc++) {
        const int buf = cc & 1;
        if (cc + 2 < NC) CP_WAIT1(); else CP_WAIT0();
        __syncthreads();

        #pragma unroll
        for (int ks = 0; ks < 4; ks++) {
            // B frags: 2 x ldmatrix.x4 -> 4 n-tiles
            uint32_t b[4][2];
            #pragma unroll
            for (int p = 0; p < 2; p++) {
                uint32_t addr = sbase +
                    b_off(buf, nn_w + p * 16 + b_row_l, 2 * ks + b_ks_l);
                LDSM_X4(b[2*p][0], b[2*p][1], b[2*p+1][0], b[2*p+1][1], addr);
            }
            // A frags + mma per (t, mtile)
            #pragma unroll
            for (int t = 0; t < TT; t++) {
                #pragma unroll
                for (int m = 0; m < 2; m++) {
                    uint32_t a[4];
                    uint32_t addr = sbase +
                        a_off(buf, t, sm_w + m * 16 + a_row_l, 2 * ks + a_ks_l);
                    LDSM_X4(a[0], a[1], a[2], a[3], addr);
                    #pragma unroll
                    for (int n = 0; n < 4; n++)
                        MMA16816(acc[t][m][n], a, b[n]);
                }
            }
        }

        __syncthreads();
        if (cc + 2 < NC) load_chunk(cc + 2, buf);
    }

    // -------- epilogue: PLIF scan over t (per-thread, in-register) --------
    const float alpha = alphap[0];
    #pragma unroll
    for (int m = 0; m < 2; m++)
        #pragma unroll
        for (int n = 0; n < 4; n++)
            #pragma unroll
            for (int e = 0; e < 4; e++) {
                float v = 0.f;
                #pragma unroll
                for (int t = 0; t < TT; t++) {
                    v += alpha * (acc[t][m][n][e] - v);
                    bool sp = (v >= 1.0f);
                    acc[t][m][n][e] = sp ? 1.0f : 0.0f;
                    v = sp ? 0.f : v;
                }
            }

    // store spikes. acc element layout: e0,e1 -> row lane/4, cols 2c,2c+1;
    // e2,e3 -> row lane/4 + 8.
    const int row_in_m = lane >> 2;
    const int col_pair = (lane & 3) * 2;
    #pragma unroll
    for (int t = 0; t < TT; t++)
        #pragma unroll
        for (int m = 0; m < 2; m++)
            #pragma unroll
            for (int rh = 0; rh < 2; rh++) {
                int site = bm0 + sm_w + m * 16 + row_in_m + rh * 8;
                #pragma unroll
                for (int n = 0; n < 4; n++) {
                    int col = bn0 + nn_w + n * 8 + col_pair;
                    float s0 = acc[t][m][n][rh * 2];
                    float s1v = acc[t][m][n][rh * 2 + 1];
                    size_t base = ((size_t)t * BROWS + site) * (size_t)NG + col;
                    if (OUTF32) {
                        *(float2*)((float*)outp + base) = make_float2(s0, s1v);
                    } else {
                        uint32_t pk = (s0 != 0.f ? 0x3F80u : 0u) |
                                      (s1v != 0.f ? 0x3F800000u : 0u);
                        *(uint32_t*)((__nv_bfloat16*)outp + base) = pk;
                    }
                }
            }
}

// ---------------- launch ----------------
extern "C" void kernel_launch(void* const* d_in, const int* in_sizes, int n_in,
                              void* d_out, int out_size)
{
    const float* x  = (const float*)d_in[0];   // [T,B,N,D]
    const float* W1 = (const float*)d_in[1];   // [H,D]
    const float* W2 = (const float*)d_in[2];   // [D,H]
    const float* a1 = (const float*)d_in[3];
    const float* a2 = (const float*)d_in[4];
    float* out = (float*)d_out;                // [T,B,N,D] fp32

    __nv_bfloat16 *xs, *w1p, *w2p, *s1;
    cudaGetSymbolAddress((void**)&xs,  g_xs);
    cudaGetSymbolAddress((void**)&w1p, g_w1);
    cudaGetSymbolAddress((void**)&w2p, g_w2);
    cudaGetSymbolAddress((void**)&s1,  g_s1);

    cudaFuncSetAttribute(gemm_plif<0>, cudaFuncAttributeMaxDynamicSharedMemorySize, SMEM_BYTES);
    cudaFuncSetAttribute(gemm_plif<1>, cudaFuncAttributeMaxDynamicSharedMemorySize, SMEM_BYTES);

    split_x_kernel<<<(TT * BROWS * DD) / 256, 256>>>(x, xs);
    pack_w1_kernel<<<(HH * DD) / 256, 256>>>(W1, w1p);
    pack_w2_kernel<<<(DD * HH) / 256, 256>>>(W2, w2p);

    // layer 1: A=[T,8192,1024(wrap)] x B=[2048,1536] -> s1 bf16 spikes
    dim3 g1(BROWS / MS, HH / TN);   // 128 x 16
    gemm_plif<0><<<g1, 256, SMEM_BYTES>>>(xs, w1p, a1, (void*)s1, KA1, KB1, HH);

    // layer 2: A=[T,8192,2048(wrap)] x B=[512,4096] -> out fp32 spikes
    dim3 g2(BROWS / MS, DD / TN);   // 128 x 4
    gemm_plif<1><<<g2, 256, SMEM_BYTES>>>(s1, w2p, a2, (void*)out, KA2, KB2, DD);
}

// round 4
// speedup vs baseline: 3.2442x; 1.0197x over previous
#include <cuda_runtime.h>
#include <cuda_bf16.h>
#include <cstdint>
#include <cstddef>

// ---------------- problem dims ----------------
constexpr int TT    = 4;
constexpr int BROWS = 8192;           // B*N
constexpr int DD    = 512;
constexpr int HH    = 2048;
constexpr int KA1   = 1024;           // layer1 A cols: [hi(512) | lo(512)]
constexpr int KB1   = 1536;           // layer1 extended K
constexpr int KA2   = 2048;           // layer2 A cols (s1, exact bf16)
constexpr int KB2   = 4096;           // layer2 extended K: W2 [hi|lo]

// tile config
constexpr int MS  = 64;    // sites per CTA
constexpr int TN  = 128;   // output cols per CTA
constexpr int BK  = 64;    // k per smem stage (128 bytes bf16)
constexpr int STG = 4;     // pipeline stages

// smem: per stage A = 4t x 64 x 128B = 32768, B = 128 x 128B = 16384
constexpr uint32_t A_STAGE = 32768;
constexpr uint32_t B_STAGE = 16384;
constexpr uint32_t SM_B_OFF = STG * A_STAGE;              // 131072
constexpr uint32_t SMEM_BYTES = STG * (A_STAGE + B_STAGE); // 196608

// ---------------- scratch (static device arrays) ----------------
__device__ __nv_bfloat16 g_xs[(size_t)TT * BROWS * KA1];   // x split [hi|lo]
__device__ __nv_bfloat16 g_w1[(size_t)HH * KB1];           // [hi|hi|lo]
__device__ __nv_bfloat16 g_w2[(size_t)DD * KB2];           // [hi|lo]
__device__ __nv_bfloat16 g_s1[(size_t)TT * BROWS * HH];    // spikes layer1 (exact)

// ---------------- PTX helpers ----------------
__device__ __forceinline__ uint32_t smem_u32(const void* p) {
    uint32_t a;
    asm("{ .reg .u64 t; cvta.to.shared.u64 t, %1; cvt.u32.u64 %0, t; }" : "=r"(a) : "l"(p));
    return a;
}
#define CP_ASYNC16(dst, src) \
    asm volatile("cp.async.cg.shared.global [%0], [%1], 16;" :: "r"(dst), "l"(src) : "memory")
#define CP_COMMIT() asm volatile("cp.async.commit_group;" ::: "memory")

#define LDSM_X4(r0, r1, r2, r3, addr)                                        \
    asm volatile("ldmatrix.sync.aligned.m8n8.x4.shared.b16 {%0,%1,%2,%3}, [%4];" \
        : "=r"(r0), "=r"(r1), "=r"(r2), "=r"(r3) : "r"(addr))

#define MMA16816(d, a, b)                                                    \
    asm volatile("mma.sync.aligned.m16n8k16.row.col.f32.bf16.bf16.f32 "      \
        "{%0,%1,%2,%3}, {%4,%5,%6,%7}, {%8,%9}, {%0,%1,%2,%3};"              \
        : "+f"((d)[0]), "+f"((d)[1]), "+f"((d)[2]), "+f"((d)[3])             \
        : "r"((a)[0]), "r"((a)[1]), "r"((a)[2]), "r"((a)[3]),                \
          "r"((b)[0]), "r"((b)[1]))

// smem offsets, XOR swizzle: 128B rows, 8 x 16B segments, kseg ^= row&7
__device__ __forceinline__ uint32_t a_off(int buf, int t, int site, int kseg) {
    return buf * A_STAGE + t * 8192 + site * 128 + ((kseg ^ (site & 7)) << 4);
}
__device__ __forceinline__ uint32_t b_off(int buf, int n, int kseg) {
    return SM_B_OFF + buf * B_STAGE + n * 128 + ((kseg ^ (n & 7)) << 4);
}

// ---------------- split/pack kernels (vectorized) ----------------
__global__ void split_x_kernel(const float4* __restrict__ x, __nv_bfloat16* __restrict__ xs)
{
    size_t i = (size_t)blockIdx.x * blockDim.x + threadIdx.x;   // over 32768*128 float4s
    float4 v = x[i];
    int r = (int)(i >> 7);
    int d = ((int)i & 127) * 4;
    __nv_bfloat16 h0 = __float2bfloat16(v.x), h1 = __float2bfloat16(v.y);
    __nv_bfloat16 h2 = __float2bfloat16(v.z), h3 = __float2bfloat16(v.w);
    __nv_bfloat162* hp = (__nv_bfloat162*)(xs + (size_t)r * KA1 + d);
    hp[0] = __nv_bfloat162(h0, h1);
    hp[1] = __nv_bfloat162(h2, h3);
    __nv_bfloat162* lp = (__nv_bfloat162*)(xs + (size_t)r * KA1 + 512 + d);
    lp[0] = __nv_bfloat162(__float2bfloat16(v.x - __bfloat162float(h0)),
                           __float2bfloat16(v.y - __bfloat162float(h1)));
    lp[1] = __nv_bfloat162(__float2bfloat16(v.z - __bfloat162float(h2)),
                           __float2bfloat16(v.w - __bfloat162float(h3)));
}
__global__ void pack_w1_kernel(const float* __restrict__ w, __nv_bfloat16* __restrict__ o)
{
    size_t i = (size_t)blockIdx.x * blockDim.x + threadIdx.x;   // 2048*512
    int r = (int)(i >> 9);
    int d = (int)(i & 511);
    float v = w[i];
    __nv_bfloat16 hi = __float2bfloat16(v);
    float lo = v - __bfloat162float(hi);
    o[(size_t)r * KB1 + d]        = hi;
    o[(size_t)r * KB1 + 512 + d]  = hi;
    o[(size_t)r * KB1 + 1024 + d] = __float2bfloat16(lo);
}
__global__ void pack_w2_kernel(const float* __restrict__ w, __nv_bfloat16* __restrict__ o)
{
    size_t i = (size_t)blockIdx.x * blockDim.x + threadIdx.x;   // 512*2048
    int r = (int)(i >> 11);
    int c = (int)(i & 2047);
    float v = w[i];
    __nv_bfloat16 hi = __float2bfloat16(v);
    float lo = v - __bfloat162float(hi);
    o[(size_t)r * KB2 + c]        = hi;
    o[(size_t)r * KB2 + 2048 + c] = __float2bfloat16(lo);
}

// ---------------- fused mma.sync GEMM + PLIF ----------------
// 512 threads, 16 warps: 4 over sites (16 each), 4 over cols (32 each).
// A [TT][BROWS][KA] bf16 (K wraps mod KA), Bw [NG][KB] bf16.
template<int OUTF32>
__global__ __launch_bounds__(512, 1)
void gemm_plif(const __nv_bfloat16* __restrict__ A,
               const __nv_bfloat16* __restrict__ Bw,
               const float* __restrict__ alphap,
               void* __restrict__ outp,
               int KA, int KB, int NG)
{
    extern __shared__ __align__(128) unsigned char smem_raw[];
    const uint32_t sbase = smem_u32(smem_raw);

    const int tid  = threadIdx.x;
    const int lane = tid & 31;
    const int wid  = tid >> 5;          // 0..15
    const int wm   = wid & 3;           // 4 warps over sites
    const int wn   = wid >> 2;          // 4 warps over cols
    const int sm_w = wm * 16;           // warp site base
    const int nn_w = wn * 32;           // warp col base

    const int bm0 = blockIdx.x * MS;
    const int bn0 = blockIdx.y * TN;
    const int NC  = KB / BK;

    auto load_chunk = [&](int cc, int buf) {
        const int acol = (cc * BK) % KA;
        const int bcol = cc * BK;
        #pragma unroll
        for (int i = tid; i < 2048; i += 512) {      // A: 4t*64*8 segs
            int kseg = i & 7, site = (i >> 3) & 63, t = i >> 9;
            const __nv_bfloat16* g =
                A + ((size_t)t * BROWS + bm0 + site) * KA + acol + kseg * 8;
            CP_ASYNC16(sbase + a_off(buf, t, site, kseg), g);
        }
        #pragma unroll
        for (int i = tid; i < 1024; i += 512) {      // B: 128*8 segs
            int kseg = i & 7, n = i >> 3;
            const __nv_bfloat16* g =
                Bw + (size_t)(bn0 + n) * KB + bcol + kseg * 8;
            CP_ASYNC16(sbase + b_off(buf, n, kseg), g);
        }
        CP_COMMIT();
    };

    float acc[TT][4][4];                 // [t][ntile][4]
    #pragma unroll
    for (int t = 0; t < TT; t++)
        #pragma unroll
        for (int n = 0; n < 4; n++)
            #pragma unroll
            for (int e = 0; e < 4; e++) acc[t][n][e] = 0.f;

    load_chunk(0, 0);
    load_chunk(1, 1);
    load_chunk(2, 2);

    // ldmatrix lane addressing (mappings proven in round 3)
    const int a_row_l = lane & 15;
    const int a_ks_l  = lane >> 4;
    const int b_row_l = (lane & 7) + ((lane & 16) >> 1);
    const int b_ks_l  = (lane >> 3) & 1;

    for (int cc = 0; cc < NC; cc++) {
        const int buf = cc & (STG - 1);
        const int rem = NC - 1 - cc;
        if (rem >= 2)      asm volatile("cp.async.wait_group 2;" ::: "memory");
        else if (rem == 1) asm volatile("cp.async.wait_group 1;" ::: "memory");
        else               asm volatile("cp.async.wait_group 0;" ::: "memory");
        __syncthreads();

        // buffer (cc+3)&3 was consumed at cc-1 (all warps past it via barrier)
        if (cc + 3 < NC) load_chunk(cc + 3, (cc + 3) & (STG - 1));

        #pragma unroll
        for (int ks = 0; ks < 4; ks++) {
            uint32_t b[4][2];
            #pragma unroll
            for (int p = 0; p < 2; p++) {
                uint32_t addr = sbase +
                    b_off(buf, nn_w + p * 16 + b_row_l, 2 * ks + b_ks_l);
                LDSM_X4(b[2*p][0], b[2*p][1], b[2*p+1][0], b[2*p+1][1], addr);
            }
            uint32_t a[TT][4];
            #pragma unroll
            for (int t = 0; t < TT; t++) {
                uint32_t addr = sbase +
                    a_off(buf, t, sm_w + a_row_l, 2 * ks + a_ks_l);
                LDSM_X4(a[t][0], a[t][1], a[t][2], a[t][3], addr);
            }
            #pragma unroll
            for (int t = 0; t < TT; t++)
                #pragma unroll
                for (int n = 0; n < 4; n++)
                    MMA16816(acc[t][n], a[t], b[n]);
        }
    }

    // -------- epilogue: PLIF scan over t (per-thread, in-register) --------
    const float alpha = alphap[0];
    #pragma unroll
    for (int n = 0; n < 4; n++)
        #pragma unroll
        for (int e = 0; e < 4; e++) {
            float v = 0.f;
            #pragma unroll
            for (int t = 0; t < TT; t++) {
                v += alpha * (acc[t][n][e] - v);
                bool sp = (v >= 1.0f);
                acc[t][n][e] = sp ? 1.0f : 0.0f;
                v = sp ? 0.f : v;
            }
        }

    // store spikes. e0,e1 -> row lane/4, cols 2c,2c+1; e2,e3 -> row+8.
    const int row_in_m = lane >> 2;
    const int col_pair = (lane & 3) * 2;
    #pragma unroll
    for (int t = 0; t < TT; t++)
        #pragma unroll
        for (int rh = 0; rh < 2; rh++) {
            int site = bm0 + sm_w + row_in_m + rh * 8;
            #pragma unroll
            for (int n = 0; n < 4; n++) {
                int col = bn0 + nn_w + n * 8 + col_pair;
                float s0  = acc[t][n][rh * 2];
                float s1v = acc[t][n][rh * 2 + 1];
                size_t base = ((size_t)t * BROWS + site) * (size_t)NG + col;
                if (OUTF32) {
                    *(float2*)((float*)outp + base) = make_float2(s0, s1v);
                } else {
                    uint32_t pk = (s0 != 0.f ? 0x3F80u : 0u) |
                                  (s1v != 0.f ? 0x3F800000u : 0u);
                    *(uint32_t*)((__nv_bfloat16*)outp + base) = pk;
                }
            }
        }
}

// ---------------- launch ----------------
extern "C" void kernel_launch(void* const* d_in, const int* in_sizes, int n_in,
                              void* d_out, int out_size)
{
    const float* x  = (const float*)d_in[0];   // [T,B,N,D]
    const float* W1 = (const float*)d_in[1];   // [H,D]
    const float* W2 = (const float*)d_in[2];   // [D,H]
    const float* a1 = (const float*)d_in[3];
    const float* a2 = (const float*)d_in[4];
    float* out = (float*)d_out;                // [T,B,N,D] fp32

    __nv_bfloat16 *xs, *w1p, *w2p, *s1;
    cudaGetSymbolAddress((void**)&xs,  g_xs);
    cudaGetSymbolAddress((void**)&w1p, g_w1);
    cudaGetSymbolAddress((void**)&w2p, g_w2);
    cudaGetSymbolAddress((void**)&s1,  g_s1);

    cudaFuncSetAttribute(gemm_plif<0>, cudaFuncAttributeMaxDynamicSharedMemorySize, SMEM_BYTES);
    cudaFuncSetAttribute(gemm_plif<1>, cudaFuncAttributeMaxDynamicSharedMemorySize, SMEM_BYTES);

    split_x_kernel<<<(TT * BROWS * DD / 4) / 256, 256>>>((const float4*)x, xs);
    pack_w1_kernel<<<(HH * DD) / 256, 256>>>(W1, w1p);
    pack_w2_kernel<<<(DD * HH) / 256, 256>>>(W2, w2p);

    // layer 1: A=[T,8192,1024(wrap)] x B=[2048,1536] -> s1 bf16 spikes
    dim3 g1(BROWS / MS, HH / TN);   // 128 x 16
    gemm_plif<0><<<g1, 512, SMEM_BYTES>>>(xs, w1p, a1, (void*)s1, KA1, KB1, HH);

    // layer 2: A=[T,8192,2048(wrap)] x B=[512,4096] -> out fp32 spikes
    dim3 g2(BROWS / MS, DD / TN);   // 128 x 4
    gemm_plif<1><<<g2, 512, SMEM_BYTES>>>(s1, w2p, a2, (void*)out, KA2, KB2, DD);
}

// round 5
// speedup vs baseline: 3.3117x; 1.0208x over previous
#include <cuda_runtime.h>
#include <cuda_bf16.h>
#include <cstdint>
#include <cstddef>

// ---------------- problem dims ----------------
constexpr int TT    = 4;
constexpr int BROWS = 8192;           // B*N
constexpr int DD    = 512;
constexpr int HH    = 2048;
constexpr int KA1   = 1024;           // layer1 A cols: [hi(512) | lo(512)]
constexpr int KB1   = 1536;           // layer1 extended K
constexpr int KA2   = 2048;           // layer2 A cols (s1, exact bf16)
constexpr int KB2   = 4096;           // layer2 extended K: W2 [hi|lo]

// tile config: CTA = 32 sites x 128 cols x 4t, 8 warps (warp = 16 x 32 x 4t)
constexpr int MS  = 32;    // sites per CTA
constexpr int TN  = 128;   // output cols per CTA
constexpr int BK  = 64;    // k per smem stage (128 bytes bf16)
constexpr int STG = 3;     // pipeline stages

// smem per stage: A = 4t x 32 x 128B = 16384, B = 128 x 128B = 16384
constexpr uint32_t A_STAGE  = 16384;
constexpr uint32_t B_STAGE  = 16384;
constexpr uint32_t SM_B_OFF = STG * A_STAGE;               // 49152
constexpr uint32_t SMEM_BYTES = STG * (A_STAGE + B_STAGE); // 98304 (2 CTAs/SM)

// ---------------- scratch (static device arrays) ----------------
__device__ __nv_bfloat16 g_xs[(size_t)TT * BROWS * KA1];   // x split [hi|lo]
__device__ __nv_bfloat16 g_w1[(size_t)HH * KB1];           // [hi|hi|lo]
__device__ __nv_bfloat16 g_w2[(size_t)DD * KB2];           // [hi|lo]
__device__ __nv_bfloat16 g_s1[(size_t)TT * BROWS * HH];    // spikes layer1 (exact)

// ---------------- PTX helpers ----------------
__device__ __forceinline__ uint32_t smem_u32(const void* p) {
    uint32_t a;
    asm("{ .reg .u64 t; cvta.to.shared.u64 t, %1; cvt.u32.u64 %0, t; }" : "=r"(a) : "l"(p));
    return a;
}
#define CP_ASYNC16(dst, src) \
    asm volatile("cp.async.cg.shared.global [%0], [%1], 16;" :: "r"(dst), "l"(src) : "memory")
#define CP_COMMIT() asm volatile("cp.async.commit_group;" ::: "memory")

#define LDSM_X4(r0, r1, r2, r3, addr)                                        \
    asm volatile("ldmatrix.sync.aligned.m8n8.x4.shared.b16 {%0,%1,%2,%3}, [%4];" \
        : "=r"(r0), "=r"(r1), "=r"(r2), "=r"(r3) : "r"(addr))

#define MMA16816(d, a, b)                                                    \
    asm volatile("mma.sync.aligned.m16n8k16.row.col.f32.bf16.bf16.f32 "      \
        "{%0,%1,%2,%3}, {%4,%5,%6,%7}, {%8,%9}, {%0,%1,%2,%3};"              \
        : "+f"((d)[0]), "+f"((d)[1]), "+f"((d)[2]), "+f"((d)[3])             \
        : "r"((a)[0]), "r"((a)[1]), "r"((a)[2]), "r"((a)[3]),                \
          "r"((b)[0]), "r"((b)[1]))

// smem offsets, XOR swizzle: 128B rows, 8 x 16B segments, kseg ^= row&7
__device__ __forceinline__ uint32_t a_off(int buf, int t, int site, int kseg) {
    return buf * A_STAGE + t * 4096 + site * 128 + ((kseg ^ (site & 7)) << 4);
}
__device__ __forceinline__ uint32_t b_off(int buf, int n, int kseg) {
    return SM_B_OFF + buf * B_STAGE + n * 128 + ((kseg ^ (n & 7)) << 4);
}

// ---------------- split/pack kernels (vectorized) ----------------
__global__ void split_x_kernel(const float4* __restrict__ x, __nv_bfloat16* __restrict__ xs)
{
    size_t i = (size_t)blockIdx.x * blockDim.x + threadIdx.x;   // 32768*128 float4s
    float4 v = x[i];
    int r = (int)(i >> 7);
    int d = ((int)i & 127) * 4;
    __nv_bfloat16 h0 = __float2bfloat16(v.x), h1 = __float2bfloat16(v.y);
    __nv_bfloat16 h2 = __float2bfloat16(v.z), h3 = __float2bfloat16(v.w);
    __nv_bfloat162* hp = (__nv_bfloat162*)(xs + (size_t)r * KA1 + d);
    hp[0] = __nv_bfloat162(h0, h1);
    hp[1] = __nv_bfloat162(h2, h3);
    __nv_bfloat162* lp = (__nv_bfloat162*)(xs + (size_t)r * KA1 + 512 + d);
    lp[0] = __nv_bfloat162(__float2bfloat16(v.x - __bfloat162float(h0)),
                           __float2bfloat16(v.y - __bfloat162float(h1)));
    lp[1] = __nv_bfloat162(__float2bfloat16(v.z - __bfloat162float(h2)),
                           __float2bfloat16(v.w - __bfloat162float(h3)));
}
__global__ void pack_w1_kernel(const float* __restrict__ w, __nv_bfloat16* __restrict__ o)
{
    size_t i = (size_t)blockIdx.x * blockDim.x + threadIdx.x;   // 2048*512
    int r = (int)(i >> 9);
    int d = (int)(i & 511);
    float v = w[i];
    __nv_bfloat16 hi = __float2bfloat16(v);
    float lo = v - __bfloat162float(hi);
    o[(size_t)r * KB1 + d]        = hi;
    o[(size_t)r * KB1 + 512 + d]  = hi;
    o[(size_t)r * KB1 + 1024 + d] = __float2bfloat16(lo);
}
__global__ void pack_w2_kernel(const float* __restrict__ w, __nv_bfloat16* __restrict__ o)
{
    size_t i = (size_t)blockIdx.x * blockDim.x + threadIdx.x;   // 512*2048
    int r = (int)(i >> 11);
    int c = (int)(i & 2047);
    float v = w[i];
    __nv_bfloat16 hi = __float2bfloat16(v);
    float lo = v - __bfloat162float(hi);
    o[(size_t)r * KB2 + c]        = hi;
    o[(size_t)r * KB2 + 2048 + c] = __float2bfloat16(lo);
}

// ---------------- fused mma.sync GEMM + PLIF ----------------
// 256 threads, 8 warps: 2 over sites (16 each), 4 over cols (32 each).
// 2 CTAs/SM (regs capped at 128) -> decoupled barrier domains.
template<int OUTF32>
__global__ __launch_bounds__(256, 2)
void gemm_plif(const __nv_bfloat16* __restrict__ A,
               const __nv_bfloat16* __restrict__ Bw,
               const float* __restrict__ alphap,
               void* __restrict__ outp,
               int KA, int KB, int NG)
{
    extern __shared__ __align__(128) unsigned char smem_raw[];
    const uint32_t sbase = smem_u32(smem_raw);

    const int tid  = threadIdx.x;
    const int lane = tid & 31;
    const int wid  = tid >> 5;          // 0..7
    const int wm   = wid & 1;           // 2 warps over sites
    const int wn   = wid >> 1;          // 4 warps over cols
    const int sm_w = wm * 16;           // warp site base
    const int nn_w = wn * 32;           // warp col base

    const int bm0 = blockIdx.x * MS;
    const int bn0 = blockIdx.y * TN;
    const int NC  = KB / BK;

    auto load_chunk = [&](int cc, int buf) {
        const int acol = (cc * BK) % KA;
        const int bcol = cc * BK;
        #pragma unroll
        for (int i = tid; i < 1024; i += 256) {      // A: 4t*32*8 segs
            int kseg = i & 7, site = (i >> 3) & 31, t = i >> 8;
            const __nv_bfloat16* g =
                A + ((size_t)t * BROWS + bm0 + site) * KA + acol + kseg * 8;
            CP_ASYNC16(sbase + a_off(buf, t, site, kseg), g);
        }
        #pragma unroll
        for (int i = tid; i < 1024; i += 256) {      // B: 128*8 segs
            int kseg = i & 7, n = i >> 3;
            const __nv_bfloat16* g =
                Bw + (size_t)(bn0 + n) * KB + bcol + kseg * 8;
            CP_ASYNC16(sbase + b_off(buf, n, kseg), g);
        }
        CP_COMMIT();
    };

    float acc[TT][4][4];                 // [t][ntile][4]
    #pragma unroll
    for (int t = 0; t < TT; t++)
        #pragma unroll
        for (int n = 0; n < 4; n++)
            #pragma unroll
            for (int e = 0; e < 4; e++) acc[t][n][e] = 0.f;

    load_chunk(0, 0);
    load_chunk(1, 1);

    // ldmatrix lane addressing (mappings proven in rounds 3-4)
    const int a_row_l = lane & 15;
    const int a_ks_l  = lane >> 4;
    const int b_row_l = (lane & 7) + ((lane & 16) >> 1);
    const int b_ks_l  = (lane >> 3) & 1;

    for (int cc = 0; cc < NC; cc++) {
        const int buf = cc % STG;
        if (cc < NC - 1) asm volatile("cp.async.wait_group 1;" ::: "memory");
        else             asm volatile("cp.async.wait_group 0;" ::: "memory");
        __syncthreads();

        // buffer (cc+2)%3 == buffer of cc-1, consumed before this barrier
        if (cc + 2 < NC) load_chunk(cc + 2, (cc + 2) % STG);

        #pragma unroll
        for (int ks = 0; ks < 4; ks++) {
            uint32_t b[4][2];
            #pragma unroll
            for (int p = 0; p < 2; p++) {
                uint32_t addr = sbase +
                    b_off(buf, nn_w + p * 16 + b_row_l, 2 * ks + b_ks_l);
                LDSM_X4(b[2*p][0], b[2*p][1], b[2*p+1][0], b[2*p+1][1], addr);
            }
            uint32_t a[TT][4];
            #pragma unroll
            for (int t = 0; t < TT; t++) {
                uint32_t addr = sbase +
                    a_off(buf, t, sm_w + a_row_l, 2 * ks + a_ks_l);
                LDSM_X4(a[t][0], a[t][1], a[t][2], a[t][3], addr);
            }
            #pragma unroll
            for (int t = 0; t < TT; t++)
                #pragma unroll
                for (int n = 0; n < 4; n++)
                    MMA16816(acc[t][n], a[t], b[n]);
        }
    }

    // -------- epilogue: PLIF scan over t (per-thread, in-register) --------
    const float alpha = alphap[0];
    #pragma unroll
    for (int n = 0; n < 4; n++)
        #pragma unroll
        for (int e = 0; e < 4; e++) {
            float v = 0.f;
            #pragma unroll
            for (int t = 0; t < TT; t++) {
                v += alpha * (acc[t][n][e] - v);
                bool sp = (v >= 1.0f);
                acc[t][n][e] = sp ? 1.0f : 0.0f;
                v = sp ? 0.f : v;
            }
        }

    // store spikes. e0,e1 -> row lane/4, cols 2c,2c+1; e2,e3 -> row+8.
    const int row_in_m = lane >> 2;
    const int col_pair = (lane & 3) * 2;
    #pragma unroll
    for (int t = 0; t < TT; t++)
        #pragma unroll
        for (int rh = 0; rh < 2; rh++) {
            int site = bm0 + sm_w + row_in_m + rh * 8;
            #pragma unroll
            for (int n = 0; n < 4; n++) {
                int col = bn0 + nn_w + n * 8 + col_pair;
                float s0  = acc[t][n][rh * 2];
                float s1v = acc[t][n][rh * 2 + 1];
                size_t base = ((size_t)t * BROWS + site) * (size_t)NG + col;
                if (OUTF32) {
                    *(float2*)((float*)outp + base) = make_float2(s0, s1v);
                } else {
                    uint32_t pk = (s0 != 0.f ? 0x3F80u : 0u) |
                                  (s1v != 0.f ? 0x3F800000u : 0u);
                    *(uint32_t*)((__nv_bfloat16*)outp + base) = pk;
                }
            }
        }
}

// ---------------- launch ----------------
extern "C" void kernel_launch(void* const* d_in, const int* in_sizes, int n_in,
                              void* d_out, int out_size)
{
    const float* x  = (const float*)d_in[0];   // [T,B,N,D]
    const float* W1 = (const float*)d_in[1];   // [H,D]
    const float* W2 = (const float*)d_in[2];   // [D,H]
    const float* a1 = (const float*)d_in[3];
    const float* a2 = (const float*)d_in[4];
    float* out = (float*)d_out;                // [T,B,N,D] fp32

    __nv_bfloat16 *xs, *w1p, *w2p, *s1;
    cudaGetSymbolAddress((void**)&xs,  g_xs);
    cudaGetSymbolAddress((void**)&w1p, g_w1);
    cudaGetSymbolAddress((void**)&w2p, g_w2);
    cudaGetSymbolAddress((void**)&s1,  g_s1);

    cudaFuncSetAttribute(gemm_plif<0>, cudaFuncAttributeMaxDynamicSharedMemorySize, SMEM_BYTES);
    cudaFuncSetAttribute(gemm_plif<1>, cudaFuncAttributeMaxDynamicSharedMemorySize, SMEM_BYTES);

    split_x_kernel<<<(TT * BROWS * DD / 4) / 256, 256>>>((const float4*)x, xs);
    pack_w1_kernel<<<(HH * DD) / 256, 256>>>(W1, w1p);
    pack_w2_kernel<<<(DD * HH) / 256, 256>>>(W2, w2p);

    // layer 1: A=[T,8192,1024(wrap)] x B=[2048,1536] -> s1 bf16 spikes
    dim3 g1(BROWS / MS, HH / TN);   // 256 x 16
    gemm_plif<0><<<g1, 256, SMEM_BYTES>>>(xs, w1p, a1, (void*)s1, KA1, KB1, HH);

    // layer 2: A=[T,8192,2048(wrap)] x B=[512,4096] -> out fp32 spikes
    dim3 g2(BROWS / MS, DD / TN);   // 256 x 4
    gemm_plif<1><<<g2, 256, SMEM_BYTES>>>(s1, w2p, a2, (void*)out, KA2, KB2, DD);
}